// round 1
// baseline (speedup 1.0000x reference)
#include <cuda_runtime.h>
#include <stdint.h>

// MXFP (E2M1, group=32) quantize-dequantize.
// x: [4,32,2048,128] fp32, groups of 32 contiguous along the last dim.
// Per group: scale = 2^(floor(log2(max|x|)) - 2); per element: quantize
// x/scale to E2M1 (RNE on the mantissa), clamp [0.5, 6], flush |xd|<=0.25
// to zero, re-apply sign, multiply back by scale.
//
// All log2/exp2 done via exponent-field bit tricks (exact powers of two),
// avoiding MUFU entirely on the per-element path.

__device__ __forceinline__ float mxfp_q1(float x, float inv_scale, float scale) {
    float xd = x * inv_scale;                       // exact (power-of-two scale)
    uint32_t b  = __float_as_uint(xd);
    uint32_t eb = b & 0x7F800000u;                  // exponent field (no sign bit)
    // mans*2 = |xd| * 2^(1-e):  bits((128-e+127)<<23) = 0x7F800000 - eb
    float m2 = fabsf(xd) * __uint_as_float(0x7F800000u - eb);
    float r  = rintf(m2);                           // RNE, matches jnp.round
    // x_rnd = r * 0.5 * 2^e = r * 2^(e-1):  bits = eb - (1<<23)
    float ra = r * __uint_as_float(eb - 0x00800000u);
    ra = fminf(fmaxf(ra, 0.5f), 6.0f);              // clip to [min_repr, max_repr]
    if (fabsf(xd) <= 0.25f) ra = 0.0f;              // lim_zero flush (also kills NaN path for xd==0/denormal)
    // reapply sign of xd
    uint32_t rb = (__float_as_uint(ra) & 0x7FFFFFFFu) | (b & 0x80000000u);
    return __uint_as_float(rb) * scale;             // exact (power-of-two scale)
}

__global__ __launch_bounds__(256) void mxfp_kernel(const float4* __restrict__ in,
                                                   float4* __restrict__ out,
                                                   int n4) {
    int i = blockIdx.x * blockDim.x + threadIdx.x;
    if (i >= n4) return;

    float4 v = in[i];

    // local max|.| over 4 elements
    float m = fmaxf(fmaxf(fabsf(v.x), fabsf(v.y)), fmaxf(fabsf(v.z), fabsf(v.w)));
    // reduce across the 8 lanes that form one group of 32 elements
    m = fmaxf(m, __shfl_xor_sync(0xFFFFFFFFu, m, 1));
    m = fmaxf(m, __shfl_xor_sync(0xFFFFFFFFu, m, 2));
    m = fmaxf(m, __shfl_xor_sync(0xFFFFFFFFu, m, 4));

    if (m == 0.0f) m = 1.0f;                        // x_max==0 -> 1

    int e   = (int)(__float_as_uint(m) >> 23) - 127; // floor(log2(m)) for normal m
    int pot = e - 2;                                 // - max_pot
    if (pot < -127) pot = -127;                      // clip(x_pot, -127, 128)

    float inv_scale = __uint_as_float((uint32_t)(127 - pot) << 23);   // 2^-pot (always normal)
    float scale = (pot >= -126)
                ? __uint_as_float((uint32_t)(pot + 127) << 23)        // normal 2^pot
                : __uint_as_float(0x00400000u);                       // 2^-127 denormal

    float4 o;
    o.x = mxfp_q1(v.x, inv_scale, scale);
    o.y = mxfp_q1(v.y, inv_scale, scale);
    o.z = mxfp_q1(v.z, inv_scale, scale);
    o.w = mxfp_q1(v.w, inv_scale, scale);
    out[i] = o;
}

extern "C" void kernel_launch(void* const* d_in, const int* in_sizes, int n_in,
                              void* d_out, int out_size) {
    const float4* x = (const float4*)d_in[0];
    float4* y = (float4*)d_out;
    int n4 = in_sizes[0] / 4;                        // 33,554,432 / 4 = 8,388,608
    int threads = 256;
    int blocks = (n4 + threads - 1) / threads;
    mxfp_kernel<<<blocks, threads>>>(x, y, n4);
}

// round 2
// speedup vs baseline: 1.0471x; 1.0471x over previous
#include <cuda_runtime.h>
#include <stdint.h>

// MXFP (E2M1-like, group=32) quantize-dequantize, bit-exact vs the JAX reference.
// Round 2: 4 float4 per thread from 4 contiguous slabs -> MLP=4 front-batched
// LDG.128s, 4 independent SHFL reduction chains (ILP over the 26-cyc shuffle
// latency), streaming cache hints (.cs) since data is touched exactly once.

__device__ __forceinline__ float mxfp_q1(float x, float inv_scale, float scale) {
    float xd = x * inv_scale;                       // exact (power-of-two scale)
    uint32_t b  = __float_as_uint(xd);
    uint32_t eb = b & 0x7F800000u;                  // exponent field
    // mans*2 = |xd| * 2^(1-e)
    float m2 = fabsf(xd) * __uint_as_float(0x7F800000u - eb);
    float r  = rintf(m2);                           // RNE, matches jnp.round
    // x_rnd = r * 2^(e-1)
    float ra = r * __uint_as_float(eb - 0x00800000u);
    ra = fminf(fmaxf(ra, 0.5f), 6.0f);              // clamp [min_repr, max_repr]
    if (fabsf(xd) <= 0.25f) ra = 0.0f;              // lim_zero flush (also handles xd==0)
    uint32_t rb = (__float_as_uint(ra) & 0x7FFFFFFFu) | (b & 0x80000000u);
    return __uint_as_float(rb) * scale;             // exact (power-of-two scale)
}

__global__ __launch_bounds__(256) void mxfp_kernel(const float4* __restrict__ in,
                                                   float4* __restrict__ out,
                                                   int nq) {
    int i = blockIdx.x * blockDim.x + threadIdx.x;
    if (i >= nq) return;

    // ---- front-batched loads: 4 independent LDG.128 in flight ----
    float4 v[4];
    v[0] = __ldcs(in + i);
    v[1] = __ldcs(in + i + nq);
    v[2] = __ldcs(in + i + 2 * nq);
    v[3] = __ldcs(in + i + 3 * nq);

    // ---- per-chunk local max |.| ----
    float m[4];
#pragma unroll
    for (int k = 0; k < 4; k++)
        m[k] = fmaxf(fmaxf(fabsf(v[k].x), fabsf(v[k].y)),
                     fmaxf(fabsf(v[k].z), fabsf(v[k].w)));

    // ---- 4 independent width-8 butterfly reductions (interleaved stages) ----
#pragma unroll
    for (int k = 0; k < 4; k++) m[k] = fmaxf(m[k], __shfl_xor_sync(0xFFFFFFFFu, m[k], 1));
#pragma unroll
    for (int k = 0; k < 4; k++) m[k] = fmaxf(m[k], __shfl_xor_sync(0xFFFFFFFFu, m[k], 2));
#pragma unroll
    for (int k = 0; k < 4; k++) m[k] = fmaxf(m[k], __shfl_xor_sync(0xFFFFFFFFu, m[k], 4));

#pragma unroll
    for (int k = 0; k < 4; k++) {
        float mk = (m[k] == 0.0f) ? 1.0f : m[k];
        int e   = (int)(__float_as_uint(mk) >> 23) - 127;  // floor(log2) for normal mk
        int pot = e - 2;
        if (pot < -127) pot = -127;

        float inv_scale = __uint_as_float((uint32_t)(127 - pot) << 23);   // 2^-pot
        float scale = (pot >= -126)
                    ? __uint_as_float((uint32_t)(pot + 127) << 23)        // normal 2^pot
                    : __uint_as_float(0x00400000u);                       // denormal 2^-127

        float4 o;
        o.x = mxfp_q1(v[k].x, inv_scale, scale);
        o.y = mxfp_q1(v[k].y, inv_scale, scale);
        o.z = mxfp_q1(v[k].z, inv_scale, scale);
        o.w = mxfp_q1(v[k].w, inv_scale, scale);
        __stcs(out + i + k * nq, o);
    }
}

extern "C" void kernel_launch(void* const* d_in, const int* in_sizes, int n_in,
                              void* d_out, int out_size) {
    const float4* x = (const float4*)d_in[0];
    float4* y = (float4*)d_out;
    int n4 = in_sizes[0] / 4;          // 8,388,608 float4
    int nq = n4 / 4;                   // 2,097,152 per slab (divides exactly)
    int threads = 256;
    int blocks = (nq + threads - 1) / threads;   // 8192
    mxfp_kernel<<<blocks, threads>>>(x, y, nq);
}